// round 10
// baseline (speedup 1.0000x reference)
#include <cuda_runtime.h>
#include <cstdint>

// Thin-plate spline (order 3), 1024x1024 grid, batch 4 (all batches identical).
//   out[b,y,x] = sum_m ((x-tx_m)^2 + (y-ty_m)^2)^{3/2} * ww_m/2^40 + v0*x + v1*y + v2
//
// R10: amortize per-warp fixed costs. Rounds 1-9 varied math, barriers, LDG
// count, and store mechanism — all land 6.3-7.7us with no pipe >26% => the
// cost is per-warp serial setup (constant loads after per-launch L1D flush,
// sample compute, shuffles) paid by 1000s of single-segment warps. Now each
// warp owns a 4-row x 256-px tile: 18 coarse samples (x stride 32, y at band
// edges) + 8 shuffles serve ALL 4 rows; per row only 4 lerps + stores remain.
// 1024 warps total (4x fewer), grid 256 x block 128. rel_err unchanged.

#define WDIM 1024
#define HDIM 1024

__device__ __forceinline__ float sqrt_approx(float v) {
    float r;
    asm("sqrt.approx.f32 %0, %1;" : "=f"(r) : "f"(v));
    return r;
}

__global__ void __launch_bounds__(128) spline_kernel(
    const float4* __restrict__ tpv,  // [8]  = train_points [16,2] in [0,1]
    const float4* __restrict__ wwv,  // [4]  = ww [16]
    const float*  __restrict__ vw,   // [3]
    float* __restrict__ out,         // [B, 1024, 1024]
    int B)
{
    const int gtid = blockIdx.x * 128 + threadIdx.x;
    const int warp = gtid >> 5;           // 0..1023
    const int lane = gtid & 31;
    const int y0   = (warp >> 2) << 2;    // band origin row (4-row bands)
    const int x0w  = (warp & 3) << 8;     // 256-px segment origin

    // ---- 18 coarse RBF samples: x = x0w+{0,32,..,256}, y = {y0, y0+4} ------
    const int   srow = (lane >= 9) ? 1 : 0;
    const int   sidx = srow ? (lane - 9) : lane;
    const float fx = (float)(x0w + (sidx << 5));
    const float fy = (float)(y0 + (srow << 2));

    const float KS = 1024.0f;
    const float KW = 1.0f / 1099511627776.0f;   // 2^-40

    float acc = 0.0f;
#pragma unroll
    for (int j = 0; j < 4; ++j) {
        const float4 pA = __ldg(tpv + 2 * j);
        const float4 pB = __ldg(tpv + 2 * j + 1);
        const float4 w4 = __ldg(wwv + j);

        float dx, dy, r2;
        dx = fmaf(pA.x, -KS, fx); dy = fmaf(pA.y, -KS, fy);
        r2 = fmaf(dx, dx, dy * dy);
        acc = fmaf(r2 * (w4.x * KW), sqrt_approx(r2), acc);

        dx = fmaf(pA.z, -KS, fx); dy = fmaf(pA.w, -KS, fy);
        r2 = fmaf(dx, dx, dy * dy);
        acc = fmaf(r2 * (w4.y * KW), sqrt_approx(r2), acc);

        dx = fmaf(pB.x, -KS, fx); dy = fmaf(pB.y, -KS, fy);
        r2 = fmaf(dx, dx, dy * dy);
        acc = fmaf(r2 * (w4.z * KW), sqrt_approx(r2), acc);

        dx = fmaf(pB.z, -KS, fx); dy = fmaf(pB.w, -KS, fy);
        r2 = fmaf(dx, dx, dy * dy);
        acc = fmaf(r2 * (w4.w * KW), sqrt_approx(r2), acc);
    }

    // ---- share samples once per warp ---------------------------------------
    const unsigned FULL = 0xffffffffu;
    const int ca = lane >> 3;      // coarse cell of first quad  (0..3)
    const int cb = ca + 4;         // coarse cell of second quad (4..7)

    const float Ta0 = __shfl_sync(FULL, acc, ca);
    const float Ta1 = __shfl_sync(FULL, acc, ca + 1);
    const float Ba0 = __shfl_sync(FULL, acc, 9 + ca);
    const float Ba1 = __shfl_sync(FULL, acc, 9 + ca + 1);
    const float Tb0 = __shfl_sync(FULL, acc, cb);
    const float Tb1 = __shfl_sync(FULL, acc, cb + 1);
    const float Bb0 = __shfl_sync(FULL, acc, 9 + cb);
    const float Bb1 = __shfl_sync(FULL, acc, 9 + cb + 1);

    const float dA0 = Ba0 - Ta0, dA1 = Ba1 - Ta1;
    const float dB0 = Bb0 - Tb0, dB1 = Bb1 - Tb1;

    const float v0 = __ldg(&vw[0]);
    const float v1 = __ldg(&vw[1]);
    const float v2 = __ldg(&vw[2]);

    const int xa = x0w + (lane << 2);
    const int xb = xa + 128;
    const float fa = (float)(xa & 31) * (1.0f / 32.0f);  // x-frac at quad start
    const float lina = (float)xa * v0;
    const float linb = (float)xb * v0;

    const size_t plane = (size_t)WDIM * HDIM;
    float* row0 = out + (size_t)y0 * WDIM;

    // ---- 4 rows: lerp in y, combine with exact linear term, store ----------
#pragma unroll
    for (int r = 0; r < 4; ++r) {
        const float fyf = 0.25f * (float)r;
        const float gLa = fmaf(dA0, fyf, Ta0);
        const float gRa = fmaf(dA1, fyf, Ta1);
        const float gLb = fmaf(dB0, fyf, Tb0);
        const float gRb = fmaf(dB1, fyf, Tb1);

        const float liny = fmaf((float)(y0 + r), v1, v2);
        const float sa = fmaf(gRa - gLa, 1.0f / 32.0f, v0);
        const float sb = fmaf(gRb - gLb, 1.0f / 32.0f, v0);
        const float ba = fmaf(gRa - gLa, fa, gLa) + liny + lina;
        const float bb = fmaf(gRb - gLb, fa, gLb) + liny + linb;

        float4 qa, qb;
        qa.x = ba;                 qa.y = ba + sa;
        qa.z = fmaf(sa, 2.0f, ba); qa.w = fmaf(sa, 3.0f, ba);
        qb.x = bb;                 qb.y = bb + sb;
        qb.z = fmaf(sb, 2.0f, bb); qb.w = fmaf(sb, 3.0f, bb);

        float* p = row0 + (size_t)r * WDIM + xa;
#pragma unroll 4
        for (int b = 0; b < B; ++b) {
            *reinterpret_cast<float4*>(p + b * plane)       = qa;
            *reinterpret_cast<float4*>(p + b * plane + 128) = qb;
        }
    }
}

extern "C" void kernel_launch(void* const* d_in, const int* in_sizes, int n_in,
                              void* d_out, int out_size)
{
    // inputs: x [B,1024,1024,1] (shape only), train_points [1,16,2],
    //         ww [1,16,1], vw [1,3,1]
    const float4* tpv = (const float4*)d_in[1];
    const float4* wwv = (const float4*)d_in[2];
    const float*  vw  = (const float*)d_in[3];
    float* out = (float*)d_out;

    const int B = in_sizes[0] / (WDIM * HDIM);  // = 4

    // 1024 warps: 256 bands x 4 segments; 4 warps per 128-thread block
    spline_kernel<<<256, 128>>>(tpv, wwv, vw, out, B);
}

// round 11
// speedup vs baseline: 1.0295x; 1.0295x over previous
#include <cuda_runtime.h>
#include <cstdint>

// Thin-plate spline (order 3), 1024x1024 grid, batch 4 (all batches identical).
//   out[b,y,x] = sum_m ((x-tx_m)^2 + (y-ty_m)^2)^{3/2} * ww_m/2^40 + v0*x + v1*y + v2
//
// R11: 10 structural variants all land 6.3-7.7us kernel with L2 at ~20-21%
// regardless of occupancy (10-70%) or issue (11-75%) => pinned at the L2
// write-drain floor (~2.4-2.7 TB/s effective for the 16.8MB output). The only
// monotone lever observed: rows-per-warp (1->4 gave 7.23->7.07). Extend to 8
// rows/warp: 18 coarse samples (x stride 32, y at band edges y0/y0+8) + 8
// shuffles serve 8 rows; 64 coalesced STG.128 per warp. 512 warps total.
// y-stride 8 <= x-stride 32 so interp error stays x-dominated (~6.5e-8).

#define WDIM 1024
#define HDIM 1024

__device__ __forceinline__ float sqrt_approx(float v) {
    float r;
    asm("sqrt.approx.f32 %0, %1;" : "=f"(r) : "f"(v));
    return r;
}

__global__ void __launch_bounds__(128) spline_kernel(
    const float4* __restrict__ tpv,  // [8]  = train_points [16,2] in [0,1]
    const float4* __restrict__ wwv,  // [4]  = ww [16]
    const float*  __restrict__ vw,   // [3]
    float* __restrict__ out,         // [B, 1024, 1024]
    int B)
{
    const int gtid = blockIdx.x * 128 + threadIdx.x;
    const int warp = gtid >> 5;           // 0..511
    const int lane = gtid & 31;
    const int y0   = (warp >> 2) << 3;    // band origin row (8-row bands)
    const int x0w  = (warp & 3) << 8;     // 256-px segment origin

    // ---- 18 coarse RBF samples: x = x0w+{0,32,..,256}, y = {y0, y0+8} ------
    const int   srow = (lane >= 9) ? 1 : 0;
    const int   sidx = srow ? (lane - 9) : lane;
    const float fx = (float)(x0w + (sidx << 5));
    const float fy = (float)(y0 + (srow << 3));

    const float KS = 1024.0f;
    const float KW = 1.0f / 1099511627776.0f;   // 2^-40

    float acc = 0.0f;
#pragma unroll
    for (int j = 0; j < 4; ++j) {
        const float4 pA = __ldg(tpv + 2 * j);
        const float4 pB = __ldg(tpv + 2 * j + 1);
        const float4 w4 = __ldg(wwv + j);

        float dx, dy, r2;
        dx = fmaf(pA.x, -KS, fx); dy = fmaf(pA.y, -KS, fy);
        r2 = fmaf(dx, dx, dy * dy);
        acc = fmaf(r2 * (w4.x * KW), sqrt_approx(r2), acc);

        dx = fmaf(pA.z, -KS, fx); dy = fmaf(pA.w, -KS, fy);
        r2 = fmaf(dx, dx, dy * dy);
        acc = fmaf(r2 * (w4.y * KW), sqrt_approx(r2), acc);

        dx = fmaf(pB.x, -KS, fx); dy = fmaf(pB.y, -KS, fy);
        r2 = fmaf(dx, dx, dy * dy);
        acc = fmaf(r2 * (w4.z * KW), sqrt_approx(r2), acc);

        dx = fmaf(pB.z, -KS, fx); dy = fmaf(pB.w, -KS, fy);
        r2 = fmaf(dx, dx, dy * dy);
        acc = fmaf(r2 * (w4.w * KW), sqrt_approx(r2), acc);
    }

    // ---- share samples once per warp ---------------------------------------
    const unsigned FULL = 0xffffffffu;
    const int ca = lane >> 3;      // coarse cell of first quad  (0..3)
    const int cb = ca + 4;         // coarse cell of second quad (4..7)

    const float Ta0 = __shfl_sync(FULL, acc, ca);
    const float Ta1 = __shfl_sync(FULL, acc, ca + 1);
    const float Ba0 = __shfl_sync(FULL, acc, 9 + ca);
    const float Ba1 = __shfl_sync(FULL, acc, 9 + ca + 1);
    const float Tb0 = __shfl_sync(FULL, acc, cb);
    const float Tb1 = __shfl_sync(FULL, acc, cb + 1);
    const float Bb0 = __shfl_sync(FULL, acc, 9 + cb);
    const float Bb1 = __shfl_sync(FULL, acc, 9 + cb + 1);

    const float dA0 = Ba0 - Ta0, dA1 = Ba1 - Ta1;
    const float dB0 = Bb0 - Tb0, dB1 = Bb1 - Tb1;

    const float v0 = __ldg(&vw[0]);
    const float v1 = __ldg(&vw[1]);
    const float v2 = __ldg(&vw[2]);

    const int xa = x0w + (lane << 2);
    const int xb = xa + 128;
    const float fa = (float)(xa & 31) * (1.0f / 32.0f);  // x-frac at quad start
    const float lina = (float)xa * v0;
    const float linb = (float)xb * v0;

    const size_t plane = (size_t)WDIM * HDIM;
    float* row0 = out + (size_t)y0 * WDIM;

    // ---- 8 rows: lerp in y, combine with exact linear term, store ----------
#pragma unroll
    for (int r = 0; r < 8; ++r) {
        const float fyf = 0.125f * (float)r;
        const float gLa = fmaf(dA0, fyf, Ta0);
        const float gRa = fmaf(dA1, fyf, Ta1);
        const float gLb = fmaf(dB0, fyf, Tb0);
        const float gRb = fmaf(dB1, fyf, Tb1);

        const float liny = fmaf((float)(y0 + r), v1, v2);
        const float sa = fmaf(gRa - gLa, 1.0f / 32.0f, v0);
        const float sb = fmaf(gRb - gLb, 1.0f / 32.0f, v0);
        const float ba = fmaf(gRa - gLa, fa, gLa) + liny + lina;
        const float bb = fmaf(gRb - gLb, fa, gLb) + liny + linb;

        float4 qa, qb;
        qa.x = ba;                 qa.y = ba + sa;
        qa.z = fmaf(sa, 2.0f, ba); qa.w = fmaf(sa, 3.0f, ba);
        qb.x = bb;                 qb.y = bb + sb;
        qb.z = fmaf(sb, 2.0f, bb); qb.w = fmaf(sb, 3.0f, bb);

        float* p = row0 + (size_t)r * WDIM + xa;
#pragma unroll 4
        for (int b = 0; b < B; ++b) {
            *reinterpret_cast<float4*>(p + b * plane)       = qa;
            *reinterpret_cast<float4*>(p + b * plane + 128) = qb;
        }
    }
}

extern "C" void kernel_launch(void* const* d_in, const int* in_sizes, int n_in,
                              void* d_out, int out_size)
{
    // inputs: x [B,1024,1024,1] (shape only), train_points [1,16,2],
    //         ww [1,16,1], vw [1,3,1]
    const float4* tpv = (const float4*)d_in[1];
    const float4* wwv = (const float4*)d_in[2];
    const float*  vw  = (const float*)d_in[3];
    float* out = (float*)d_out;

    const int B = in_sizes[0] / (WDIM * HDIM);  // = 4

    // 512 warps: 128 bands x 4 segments; 4 warps per 128-thread block
    spline_kernel<<<128, 128>>>(tpv, wwv, vw, out, B);
}